// round 6
// baseline (speedup 1.0000x reference)
#include <cuda_runtime.h>
#include <cstdint>

#define SEQ    512
#define BATCH  512
#define IN_DIM 128
#define NQ     8
#define D_TOT  136   // IN_DIM + NQ

// Scratch: Zx[s][b][o], o = g*8 + q
__device__ float g_zx[(size_t)SEQ * BATCH * 32];

typedef unsigned long long ull;

// --- packed fp32x2 ops (Blackwell; PTX-only) ---
__device__ __forceinline__ ull fma2(ull a, ull b, ull c) {
    ull d; asm("fma.rn.f32x2 %0, %1, %2, %3;" : "=l"(d) : "l"(a), "l"(b), "l"(c)); return d;
}
__device__ __forceinline__ ull mul2(ull a, ull b) {
    ull d; asm("mul.rn.f32x2 %0, %1, %2;" : "=l"(d) : "l"(a), "l"(b)); return d;
}
__device__ __forceinline__ ull add2(ull a, ull b) {
    ull d; asm("add.rn.f32x2 %0, %1, %2;" : "=l"(d) : "l"(a), "l"(b)); return d;
}
__device__ __forceinline__ ull pack2(float lo, float hi) {
    ull d; asm("mov.b64 %0, {%1, %2};" : "=l"(d) : "r"(__float_as_uint(lo)), "r"(__float_as_uint(hi))); return d;
}
__device__ __forceinline__ void unpack2(ull v, float& lo, float& hi) {
    unsigned a, b; asm("mov.b64 {%0, %1}, %2;" : "=r"(a), "=r"(b) : "l"(v));
    lo = __uint_as_float(a); hi = __uint_as_float(b);
}
__device__ __forceinline__ ull dup2(float x) {
    ull d; unsigned u = __float_as_uint(x);
    asm("mov.b64 %0, {%1, %1};" : "=l"(d) : "r"(u)); return d;
}
__device__ __forceinline__ float rcp_fast(float x) {
    float r; asm("rcp.approx.f32 %0, %1;" : "=f"(r) : "f"(x)); return r;
}

// ============================================================================
// Kernel 1: Zx[row][o] = sum_d x[row][d] * W[o][d] + b[o] + qp[o]
//   TWO rows per thread (unchanged from round 5).
// ============================================================================
__global__ __launch_bounds__(256) void zx_kernel(
    const float* __restrict__ x, const float* __restrict__ W,
    const float* __restrict__ b, const float* __restrict__ qp)
{
    __shared__ ulonglong2 Ws[IN_DIM * 4];
    __shared__ ulonglong2 Ws_hi[IN_DIM * 4];
    __shared__ float bias[32];

    int tid = threadIdx.x;
    float* WsF   = (float*)Ws;
    float* WsFhi = (float*)Ws_hi;
    for (int i = tid; i < IN_DIM * 32; i += 256) {
        int d = i >> 5, o = i & 31;
        float w = W[o * D_TOT + d];
        if (o < 16) WsF[d * 16 + o] = w;
        else        WsFhi[d * 16 + (o - 16)] = w;
    }
    if (tid < 32) bias[tid] = b[tid] + qp[tid];
    __syncthreads();

    int row0 = blockIdx.x * 512 + tid;
    int row1 = row0 + 256;
    const float4* xr0 = (const float4*)(x + (size_t)row0 * IN_DIM);
    const float4* xr1 = (const float4*)(x + (size_t)row1 * IN_DIM);

    ull acc0[16], acc1[16];
#pragma unroll
    for (int i = 0; i < 16; i++) { acc0[i] = 0ULL; acc1[i] = 0ULL; }

#pragma unroll 2
    for (int d4 = 0; d4 < IN_DIM / 4; d4++) {
        float4 xv0 = xr0[d4];
        float4 xv1 = xr1[d4];
        float xs0[4] = {xv0.x, xv0.y, xv0.z, xv0.w};
        float xs1[4] = {xv1.x, xv1.y, xv1.z, xv1.w};
#pragma unroll
        for (int k = 0; k < 4; k++) {
            int d = d4 * 4 + k;
            ull xa = dup2(xs0[k]);
            ull xb = dup2(xs1[k]);
            const ulonglong2* wlo = Ws    + d * 4;
            const ulonglong2* whi = Ws_hi + d * 4;
#pragma unroll
            for (int j = 0; j < 4; j++) {
                ulonglong2 wp = wlo[j];
                acc0[2 * j]     = fma2(xa, wp.x, acc0[2 * j]);
                acc0[2 * j + 1] = fma2(xa, wp.y, acc0[2 * j + 1]);
                acc1[2 * j]     = fma2(xb, wp.x, acc1[2 * j]);
                acc1[2 * j + 1] = fma2(xb, wp.y, acc1[2 * j + 1]);
            }
#pragma unroll
            for (int j = 0; j < 4; j++) {
                ulonglong2 wp = whi[j];
                acc0[8 + 2 * j]     = fma2(xa, wp.x, acc0[8 + 2 * j]);
                acc0[8 + 2 * j + 1] = fma2(xa, wp.y, acc0[8 + 2 * j + 1]);
                acc1[8 + 2 * j]     = fma2(xb, wp.x, acc1[8 + 2 * j]);
                acc1[8 + 2 * j + 1] = fma2(xb, wp.y, acc1[8 + 2 * j + 1]);
            }
        }
    }

    float4* zr0 = (float4*)(g_zx + (size_t)row0 * 32);
    float4* zr1 = (float4*)(g_zx + (size_t)row1 * 32);
#pragma unroll
    for (int j = 0; j < 8; j++) {
        float e0, e1, e2, e3;
        unpack2(acc0[2 * j], e0, e1); unpack2(acc0[2 * j + 1], e2, e3);
        zr0[j] = make_float4(e0 + bias[4 * j], e1 + bias[4 * j + 1],
                             e2 + bias[4 * j + 2], e3 + bias[4 * j + 3]);
        unpack2(acc1[2 * j], e0, e1); unpack2(acc1[2 * j + 1], e2, e3);
        zr1[j] = make_float4(e0 + bias[4 * j], e1 + bias[4 * j + 1],
                             e2 + bias[4 * j + 2], e3 + bias[4 * j + 3]);
    }
}

// ============================================================================
// Kernel 2: recurrence. 8 LANES PER BATCH: lane = bl*8 + g*2 + hf.
//   Gate combine via shfl_xor(6)/shfl_xor(2) — no shared memory at all.
//   g0 lanes own c and h for q = 4hf..4hf+3; others compute bounded garbage.
// ============================================================================
__global__ void __launch_bounds__(32, 1) rnn_kernel(
    const float* __restrict__ W, const float* __restrict__ h0,
    const float* __restrict__ c0, float* __restrict__ out)
{
    const unsigned FULL = 0xffffffffu;
    int lane = threadIdx.x;
    int hf = lane & 1;
    int g  = (lane >> 1) & 3;
    int bl = lane >> 3;                       // batch within warp 0..3
    int b  = blockIdx.x * 4 + bl;             // batch 0..511
    bool owner = (g == 0);

    // Row-packed recurrent weights: Wp[r][k] = (W[row_r][2k], W[row_r][2k+1]),
    // row_r = g*8 + 4*hf + r  (4 local rows = this lane's q's for gate g)
    ull Wp[4][4];
#pragma unroll
    for (int r = 0; r < 4; r++)
#pragma unroll
        for (int k = 0; k < 4; k++) {
            const float* wr = W + (g * 8 + 4 * hf + r) * D_TOT + IN_DIM;
            Wp[r][k] = pack2(wr[2 * k], wr[2 * k + 1]);
        }

    // h as 4 pair-packets
    ull hp[4];
#pragma unroll
    for (int k = 0; k < 4; k++) hp[k] = pack2(h0[b * 8 + 2 * k], h0[b * 8 + 2 * k + 1]);

    // c for this lane's 4 q's (meaningful on g0 lanes; bounded garbage elsewhere)
    float4 cv = *(const float4*)(c0 + b * 8 + 4 * hf);
    ull Cp0 = pack2(cv.x, cv.y);
    ull Cp1 = pack2(cv.z, cv.w);

    const float asc   = (g == 2) ? 1.0f : 0.5f;
    const float obias = (g == 2) ? 0.0f : 0.5f;
    const ull asc2 = dup2(asc), ob2 = dup2(obias);
    // CF4 tanh (gates, |x|<=1): x(105+10t)/(105+45t+t^2)
    const ull C10 = dup2(10.0f), C45 = dup2(45.0f), C105 = dup2(105.0f);
    // Pade [5/4] (cell): x(t^2+105t+945)/(15t^2+420t+945)
    const ull C15 = dup2(15.0f), C420 = dup2(420.0f), C945 = dup2(945.0f);

    const float4* zp = (const float4*)g_zx + ((size_t)b * 8 + g * 2 + hf);
    const size_t Z4STRIDE = (size_t)BATCH * 8;

    float4 zb[4];
#pragma unroll
    for (int u = 0; u < 4; u++) zb[u] = zp[(size_t)u * Z4STRIDE];

    float4* op4 = (float4*)(out + (size_t)b * 8 + 4 * hf);
    const size_t O4STRIDE = (size_t)BATCH * 2;   // float4 per timestep

    ull H0 = 0ULL, H1 = 0ULL;                    // h pairs on g0 lanes

    for (int s = 0; s < SEQ; s += 4) {
#pragma unroll
        for (int u = 0; u < 4; u++) {
            int sp = s + u + 4; sp = sp < SEQ ? sp : SEQ - 1;
            float4 zn = zp[(size_t)sp * Z4STRIDE];

            // dot per local row: packed accumulate over h pairs + horizontal add
            ull acA0 = mul2(hp[0], Wp[0][0]);
            ull acA1 = mul2(hp[0], Wp[1][0]);
            ull acA2 = mul2(hp[0], Wp[2][0]);
            ull acA3 = mul2(hp[0], Wp[3][0]);
#pragma unroll
            for (int k = 1; k < 4; k++) {
                acA0 = fma2(hp[k], Wp[0][k], acA0);
                acA1 = fma2(hp[k], Wp[1][k], acA1);
                acA2 = fma2(hp[k], Wp[2][k], acA2);
                acA3 = fma2(hp[k], Wp[3][k], acA3);
            }
            float l0, l1, l2, l3, r0, r1, r2, r3;
            unpack2(acA0, l0, r0);
            unpack2(acA1, l1, r1);
            unpack2(acA2, l2, r2);
            unpack2(acA3, l3, r3);
            float a0 = __cosf(zb[u].x + l0 + r0);
            float a1 = __cosf(zb[u].y + l1 + r1);
            float a2 = __cosf(zb[u].z + l2 + r2);
            float a3 = __cosf(zb[u].w + l3 + r3);

            // local inclusive cumprod of 4 + cross-half prefix
            float k1 = a0 * a1;
            float t23 = a2 * a3;
            float k2 = k1 * a2;
            float k3 = k1 * t23;
            float T = __shfl_xor_sync(FULL, k3, 1);
            ull M = dup2(hf ? T : 1.0f);
            ull X0 = mul2(mul2(M, pack2(a0, k1)), asc2);
            ull X1 = mul2(mul2(M, pack2(k2, k3)), asc2);

            // gate rationals: v = obias + asc * tanh(X), CF4; one rcp per packet
            ull T0 = mul2(X0, X0), T1 = mul2(X1, X1);
            ull N0 = mul2(X0, fma2(C10, T0, C105));
            ull N1 = mul2(X1, fma2(C10, T1, C105));
            ull B0 = fma2(add2(T0, C45), T0, C105);
            ull B1 = fma2(add2(T1, C45), T1, C105);
            float d0, d1, d2, d3, n0, n1, n2, n3;
            unpack2(B0, d0, d1); unpack2(B1, d2, d3);
            unpack2(N0, n0, n1); unpack2(N1, n2, n3);
            float inv0 = rcp_fast(d0 * d1);
            float inv1 = rcp_fast(d2 * d3);
            ull V0 = fma2(asc2, mul2(pack2(n0 * d1, n1 * d0), dup2(inv0)), ob2);
            ull V1 = fma2(asc2, mul2(pack2(n2 * d3, n3 * d2), dup2(inv1)), ob2);

            // gate exchange 1: xor6 swaps f<->o, i<->g (same hf, same batch)
            ull t0 = __shfl_xor_sync(FULL, V0, 6);
            ull t1 = __shfl_xor_sync(FULL, V1, 6);
            ull pr0 = mul2(V0, t0);      // on g1 lanes: i*g
            ull pr1 = mul2(V1, t1);
            // gate exchange 2: xor2 brings g1's i*g to g0
            ull ig0 = __shfl_xor_sync(FULL, pr0, 2);
            ull ig1 = __shfl_xor_sync(FULL, pr1, 2);

            // cell update (meaningful on g0; bounded elsewhere)
            Cp0 = fma2(V0, Cp0, ig0);
            Cp1 = fma2(V1, Cp1, ig1);

            // cell tanh, Pade [5/4], one rcp per packet
            ull TC0 = mul2(Cp0, Cp0), TC1 = mul2(Cp1, Cp1);
            ull NC0 = mul2(Cp0, fma2(add2(TC0, C105), TC0, C945));
            ull NC1 = mul2(Cp1, fma2(add2(TC1, C105), TC1, C945));
            ull BC0 = fma2(fma2(C15, TC0, C420), TC0, C945);
            ull BC1 = fma2(fma2(C15, TC1, C420), TC1, C945);
            float e0, e1, e2, e3, m0, m1, m2, m3;
            unpack2(BC0, e0, e1); unpack2(BC1, e2, e3);
            unpack2(NC0, m0, m1); unpack2(NC1, m2, m3);
            float iv0 = rcp_fast(e0 * e1);
            float iv1 = rcp_fast(e2 * e3);
            ull TH0 = mul2(pack2(m0 * e1, m1 * e0), dup2(iv0));
            ull TH1 = mul2(pack2(m2 * e3, m3 * e2), dup2(iv1));

            // h = o * tanh(c): on g0 lanes t0/t1 hold o (from g3 via xor6)
            H0 = mul2(t0, TH0);
            H1 = mul2(t1, TH1);

            if (owner) {
                float h0a, h0b, h1a, h1b;
                unpack2(H0, h0a, h0b);
                unpack2(H1, h1a, h1b);
                *op4 = make_float4(h0a, h0b, h1a, h1b);
            }
            op4 += O4STRIDE;

            // broadcast h pairs from the two g0 lanes of this batch group
            hp[0] = __shfl_sync(FULL, H0, 0, 8);
            hp[1] = __shfl_sync(FULL, H1, 0, 8);
            hp[2] = __shfl_sync(FULL, H0, 1, 8);
            hp[3] = __shfl_sync(FULL, H1, 1, 8);

            zb[u] = zn;
        }
    }

    // Final states: h_f then c_f (g0 lanes own q = 4hf..4hf+3)
    size_t base = (size_t)SEQ * BATCH * 8;
    if (owner) {
        float h0a, h0b, h1a, h1b, c0a, c0b, c1a, c1b;
        unpack2(H0, h0a, h0b); unpack2(H1, h1a, h1b);
        unpack2(Cp0, c0a, c0b); unpack2(Cp1, c1a, c1b);
        *(float4*)(out + base + (size_t)b * 8 + 4 * hf) =
            make_float4(h0a, h0b, h1a, h1b);
        *(float4*)(out + base + BATCH * 8 + (size_t)b * 8 + 4 * hf) =
            make_float4(c0a, c0b, c1a, c1b);
    }
}

extern "C" void kernel_launch(void* const* d_in, const int* in_sizes, int n_in,
                              void* d_out, int out_size) {
    const float* x  = (const float*)d_in[0];   // inputs (512,512,128)
    const float* h0 = (const float*)d_in[1];   // (512,8)
    const float* c0 = (const float*)d_in[2];   // (512,8)
    const float* W  = (const float*)d_in[3];   // (4,8,136)
    const float* b  = (const float*)d_in[4];   // (4,8)
    const float* qp = (const float*)d_in[5];   // (4,8)
    float* out = (float*)d_out;

    zx_kernel<<<(SEQ * BATCH) / 512, 256>>>(x, W, b, qp);
    rnn_kernel<<<BATCH / 4, 32>>>(W, h0, c0, out);
}